// round 3
// baseline (speedup 1.0000x reference)
#include <cuda_runtime.h>
#include <cuda_bf16.h>
#include <cstdint>
#include <math.h>

// Problem constants
#define BB   64
#define TT   128
#define EE   256
#define HH   256
#define BT   (BB*TT)        // 8192

// Scratch: input-drive buffer xp[B*T, HH] (8 MB), reused for level 0 then 1.
__device__ float g_xp[BT * HH];

// ---------------------------------------------------------------------------
// GEMM: g_xp[m, n] = sum_k A[row(m), k] * W[n, k] + bias[n]
// ---------------------------------------------------------------------------
__global__ __launch_bounds__(256) void gemm_xp(
    const float* __restrict__ A, const int* __restrict__ rowidx, int astride,
    const float* __restrict__ W, const float* __restrict__ bias)
{
    __shared__ float As[32][68];
    __shared__ float Bs[32][68];

    const int m0  = blockIdx.x * 64;
    const int n0  = blockIdx.y * 64;
    const int tid = threadIdx.x;
    const int lr  = tid >> 3;
    const int lk  = (tid & 7) << 2;
    const int ty  = tid >> 4;
    const int tx  = tid & 15;

    float acc[4][4] = {};

    for (int k0 = 0; k0 < 256; k0 += 32) {
        #pragma unroll
        for (int rr = 0; rr < 2; rr++) {
            int m  = m0 + lr + rr * 32;
            int ar = rowidx ? rowidx[m] : m;
            float4 a4 = *(const float4*)(A + (size_t)ar * astride + k0 + lk);
            As[lk + 0][lr + rr * 32] = a4.x;
            As[lk + 1][lr + rr * 32] = a4.y;
            As[lk + 2][lr + rr * 32] = a4.z;
            As[lk + 3][lr + rr * 32] = a4.w;

            int n = n0 + lr + rr * 32;
            float4 b4 = *(const float4*)(W + (size_t)n * 256 + k0 + lk);
            Bs[lk + 0][lr + rr * 32] = b4.x;
            Bs[lk + 1][lr + rr * 32] = b4.y;
            Bs[lk + 2][lr + rr * 32] = b4.z;
            Bs[lk + 3][lr + rr * 32] = b4.w;
        }
        __syncthreads();

        #pragma unroll
        for (int kk = 0; kk < 32; kk++) {
            float a[4], b[4];
            *(float4*)a = *(const float4*)&As[kk][ty << 2];
            *(float4*)b = *(const float4*)&Bs[kk][tx << 2];
            #pragma unroll
            for (int i = 0; i < 4; i++)
                #pragma unroll
                for (int j = 0; j < 4; j++)
                    acc[i][j] = fmaf(a[i], b[j], acc[i][j]);
        }
        __syncthreads();
    }

    float4 bv = *(const float4*)(bias + n0 + (tx << 2));
    #pragma unroll
    for (int i = 0; i < 4; i++) {
        int m = m0 + (ty << 2) + i;
        float4 o;
        o.x = acc[i][0] + bv.x;
        o.y = acc[i][1] + bv.y;
        o.z = acc[i][2] + bv.z;
        o.w = acc[i][3] + bv.w;
        *(float4*)(g_xp + (size_t)m * 256 + n0 + (tx << 2)) = o;
    }
}

// ---------------------------------------------------------------------------
// LTC scan: 4-CTA clusters, 16 clusters (64 CTAs), 4 batch elems / cluster
// processed as 2 independent software-pipelined PAIRS.
//   - Weights in registers (32 f32x2 / thread), fma.rn.f32x2 GEMV.
//   - Cross-CTA h exchange via st.async + tx-counting mbarriers; each pair has
//     TWO alternating mbarriers (even/odd step) so step t and t+1 tx bytes can
//     never mix in one phase.
//   - tanh.approx.f32 (MUFU.TANH) on the critical path.
//   - g_xp input drive prefetched one step ahead.
// ---------------------------------------------------------------------------
#define CS  4
#define NP  2           // pairs per cluster
#define SEG 68          // per-ks segment stride (floats): 64 data + 4 pad

typedef unsigned long long u64t;

__device__ __forceinline__ uint32_t smem_u32(const void* p) {
    return (uint32_t)__cvta_generic_to_shared(p);
}
__device__ __forceinline__ u64t pk2(float x, float y) {
    u64t r; asm("mov.b64 %0, {%1,%2};" : "=l"(r) : "f"(x), "f"(y)); return r;
}
__device__ __forceinline__ void fma2(u64t& d, u64t a, u64t b) {
    asm("fma.rn.f32x2 %0, %1, %2, %0;" : "+l"(d) : "l"(a), "l"(b));
}
__device__ __forceinline__ float hsum2(u64t v) {
    float a, b; asm("mov.b64 {%0,%1}, %2;" : "=f"(a), "=f"(b) : "l"(v));
    return a + b;
}
__device__ __forceinline__ float tanh_fast(float x) {
    float y; asm("tanh.approx.f32 %0, %1;" : "=f"(y) : "f"(x)); return y;
}
__device__ __forceinline__ void st_async_f32(uint32_t addr, float v, uint32_t mb) {
    asm volatile("st.async.shared::cluster.mbarrier::complete_tx::bytes.b32 [%0], %1, [%2];"
                 :: "r"(addr), "f"(v), "r"(mb) : "memory");
}
__device__ __forceinline__ void mbar_wait(uint32_t mb, uint32_t par) {
    asm volatile(
        "{ .reg .pred p;\n\t"
        "WAIT_%=:\n\t"
        "  mbarrier.try_wait.parity.acquire.cluster.shared::cta.b64 p, [%0], %1;\n\t"
        "  @!p bra WAIT_%=;\n\t"
        "}" :: "r"(mb), "r"(par) : "memory");
}

__global__ void __cluster_dims__(CS, 1, 1) __launch_bounds__(256, 1)
ltc_scan(const float* __restrict__ Wrec, const float* __restrict__ mask,
         const float* __restrict__ tau_raw, float* __restrict__ out,
         int outoff)
{
    // 3 time-buffers x 4 batch x (4*SEG) floats
    __shared__ __align__(16) float hb[3][2 * NP][4 * SEG];
    __shared__ u64t mbar[NP][2];

    uint32_t rank;
    asm("mov.u32 %0, %%cluster_ctarank;" : "=r"(rank));
    const int cl    = blockIdx.x / CS;
    const int bbase = cl * 2 * NP;          // 4 batch per cluster
    const int jbase = (int)rank * 64;

    const int tid  = threadIdx.x;
    const int lane = tid & 31;
    const int warp = tid >> 5;
    const int jl   = lane & 7;      // neuron within warp
    const int ks   = lane >> 3;     // k-slice 0..3
    const int j    = warp * 8 + jl; // local neuron 0..63
    const int jf   = jbase + j;     // global neuron 0..255
    const int kbase = ks * 64;

    const uint32_t mb00 = smem_u32(&mbar[0][0]);
    const uint32_t mb01 = smem_u32(&mbar[0][1]);
    const uint32_t mb10 = smem_u32(&mbar[1][0]);
    const uint32_t mb11 = smem_u32(&mbar[1][1]);
    if (tid == 0) {
        asm volatile("mbarrier.init.shared.b64 [%0], 1;" :: "r"(mb00) : "memory");
        asm volatile("mbarrier.init.shared.b64 [%0], 1;" :: "r"(mb01) : "memory");
        asm volatile("mbarrier.init.shared.b64 [%0], 1;" :: "r"(mb10) : "memory");
        asm volatile("mbarrier.init.shared.b64 [%0], 1;" :: "r"(mb11) : "memory");
    }

    // Zero all h buffers.
    for (int e = tid; e < 3 * 2 * NP * 4 * SEG; e += 256)
        ((float*)hb)[e] = 0.f;

    // DSMEM rank-address deltas (mapa is affine in the address).
    int32_t dsd[CS];
    #pragma unroll
    for (int c = 0; c < CS; c++) {
        uint32_t ra;
        asm("mapa.shared::cluster.u32 %0, %1, %2;" : "=r"(ra) : "r"(mb00), "r"(c));
        dsd[c] = (int32_t)(ra - mb00);
    }

    // Load this thread's 64 masked weights into registers (32 f32x2 pairs).
    u64t w2[32];
    {
        const float4* wr = (const float4*)(Wrec + (size_t)jf * HH + kbase);
        const float4* mr = (const float4*)(mask + (size_t)jf * HH + kbase);
        #pragma unroll
        for (int ii = 0; ii < 16; ii++) {
            float4 wv = __ldg(wr + ii);
            float4 mv = __ldg(mr + ii);
            w2[2 * ii + 0] = pk2(wv.x * mv.x, wv.y * mv.y);
            w2[2 * ii + 1] = pk2(wv.z * mv.z, wv.w * mv.w);
        }
    }

    const float tr     = tau_raw[jf];
    const float invtau = 1.0f / (log1pf(expf(tr)) + 0.1f);

    const bool prod = (ks == 0);
    const int  widx = jf + ((jf >> 6) << 2);   // padded slot for neuron jf

    // Per-batch pointers for xq (input drive) and output.
    const float* xp_p[2 * NP];
    float*       out_p[2 * NP];
    #pragma unroll
    for (int b = 0; b < 2 * NP; b++) {
        xp_p[b]  = g_xp + (size_t)(bbase + b) * TT * HH + jf;
        out_p[b] = out + (size_t)(bbase + b) * TT * 512 + outoff + jf;
    }

    __syncthreads();
    asm volatile("barrier.cluster.arrive.aligned;" ::: "memory");
    asm volatile("barrier.cluster.wait.aligned;"   ::: "memory");

    // Prefetch xq for t=0.
    float xq[2 * NP];
    if (prod) {
        #pragma unroll
        for (int b = 0; b < 2 * NP; b++) xq[b] = __ldg(xp_p[b]);
    }

    int wb = 0, rb = 2;

    for (int t = 0; t < TT; t++) {
        const uint32_t mbA = (t & 1) ? mb01 : mb00;
        const uint32_t mbB = (t & 1) ? mb11 : mb10;
        if (tid == 0) {
            asm volatile("mbarrier.arrive.expect_tx.shared.b64 _, [%0], 2048;"
                         :: "r"(mbA) : "memory");
            asm volatile("mbarrier.arrive.expect_tx.shared.b64 _, [%0], 2048;"
                         :: "r"(mbB) : "memory");
        }

        float* hrbase = &hb[rb][0][0];
        float* hwbase = &hb[wb][0][0];

        #pragma unroll
        for (int p = 0; p < NP; p++) {
            const float* r0 = hrbase + (2 * p + 0) * (4 * SEG);
            const float* r1 = hrbase + (2 * p + 1) * (4 * SEG);
            const ulonglong2* p0 = (const ulonglong2*)(r0 + ks * SEG);
            const ulonglong2* p1 = (const ulonglong2*)(r1 + ks * SEG);

            u64t a0 = 0, a1 = 0, c0 = 0, c1 = 0;
            #pragma unroll
            for (int ii = 0; ii < 16; ii++) {
                ulonglong2 v0 = p0[ii];
                ulonglong2 v1 = p1[ii];
                fma2(a0, w2[2 * ii + 0], v0.x);
                fma2(a1, w2[2 * ii + 1], v0.y);
                fma2(c0, w2[2 * ii + 0], v1.x);
                fma2(c1, w2[2 * ii + 1], v1.y);
            }
            float s0 = hsum2(a0) + hsum2(a1);
            float s1 = hsum2(c0) + hsum2(c1);
            s0 += __shfl_xor_sync(0xffffffffu, s0, 8);
            s0 += __shfl_xor_sync(0xffffffffu, s0, 16);
            s1 += __shfl_xor_sync(0xffffffffu, s1, 8);
            s1 += __shfl_xor_sync(0xffffffffu, s1, 16);

            if (prod) {
                float h0o = r0[widx];
                float h1o = r1[widx];
                float hn0 = fmaf(tanh_fast(s0 + xq[2 * p + 0]) - h0o, invtau, h0o);
                float hn1 = fmaf(tanh_fast(s1 + xq[2 * p + 1]) - h1o, invtau, h1o);

                out_p[2 * p + 0][(size_t)t * 512] = hn0;
                out_p[2 * p + 1][(size_t)t * 512] = hn1;

                uint32_t la0 = smem_u32(hwbase + (2 * p + 0) * (4 * SEG) + widx);
                uint32_t la1 = smem_u32(hwbase + (2 * p + 1) * (4 * SEG) + widx);
                uint32_t mbp = (p == 0) ? mbA : mbB;
                #pragma unroll
                for (int c = 0; c < CS; c++) {
                    st_async_f32(la0 + dsd[c], hn0, mbp + dsd[c]);
                    st_async_f32(la1 + dsd[c], hn1, mbp + dsd[c]);
                }
            }
        }

        // Prefetch next step's input drive while the exchange is in flight.
        if (prod && t + 1 < TT) {
            #pragma unroll
            for (int b = 0; b < 2 * NP; b++)
                xq[b] = __ldg(xp_p[b] + (size_t)(t + 1) * HH);
        }

        const uint32_t par = (uint32_t)((t >> 1) & 1);
        mbar_wait(mbA, par);
        mbar_wait(mbB, par);

        rb = wb;
        wb = (wb == 2) ? 0 : wb + 1;
    }
}

// ---------------------------------------------------------------------------
// Launch: gemm(xp0) -> scan0 -> gemm(xp1 from h0 in d_out) -> scan1
// ---------------------------------------------------------------------------
extern "C" void kernel_launch(void* const* d_in, const int* in_sizes, int n_in,
                              void* d_out, int out_size)
{
    const int*   tokens = (const int*)  d_in[0];
    const float* emb    = (const float*)d_in[1];
    const float* W_in0  = (const float*)d_in[2];
    const float* W_rec0 = (const float*)d_in[3];
    const float* b0     = (const float*)d_in[4];
    const float* tau0   = (const float*)d_in[5];
    const float* mask0  = (const float*)d_in[6];
    const float* W_in1  = (const float*)d_in[7];
    const float* W_rec1 = (const float*)d_in[8];
    const float* b1     = (const float*)d_in[9];
    const float* tau1   = (const float*)d_in[10];
    const float* mask1  = (const float*)d_in[11];
    float* out = (float*)d_out;

    (void)in_sizes; (void)n_in; (void)out_size;

    dim3 ggrid(BT / 64, HH / 64);   // 128 x 4

    gemm_xp<<<ggrid, 256>>>(emb, tokens, EE, W_in0, b0);
    ltc_scan<<<64, 256>>>(W_rec0, mask0, tau0, out, 0);
    gemm_xp<<<ggrid, 256>>>(out, nullptr, 512, W_in1, b1);
    ltc_scan<<<64, 256>>>(W_rec1, mask1, tau1, out, 256);
}

// round 4
// speedup vs baseline: 1.3591x; 1.3591x over previous
#include <cuda_runtime.h>
#include <cuda_bf16.h>
#include <cstdint>
#include <math.h>

// Problem constants
#define BB   64
#define TT   128
#define EE   256
#define HH   256
#define BT   (BB*TT)        // 8192

// Scratch: input-drive buffer xp[B*T, HH] (8 MB), reused for level 0 then 1.
__device__ float g_xp[BT * HH];

// ---------------------------------------------------------------------------
// GEMM: g_xp[m, n] = sum_k A[row(m), k] * W[n, k] + bias[n]
// ---------------------------------------------------------------------------
__global__ __launch_bounds__(256) void gemm_xp(
    const float* __restrict__ A, const int* __restrict__ rowidx, int astride,
    const float* __restrict__ W, const float* __restrict__ bias)
{
    __shared__ float As[32][68];
    __shared__ float Bs[32][68];

    const int m0  = blockIdx.x * 64;
    const int n0  = blockIdx.y * 64;
    const int tid = threadIdx.x;
    const int lr  = tid >> 3;
    const int lk  = (tid & 7) << 2;
    const int ty  = tid >> 4;
    const int tx  = tid & 15;

    float acc[4][4] = {};

    for (int k0 = 0; k0 < 256; k0 += 32) {
        #pragma unroll
        for (int rr = 0; rr < 2; rr++) {
            int m  = m0 + lr + rr * 32;
            int ar = rowidx ? rowidx[m] : m;
            float4 a4 = *(const float4*)(A + (size_t)ar * astride + k0 + lk);
            As[lk + 0][lr + rr * 32] = a4.x;
            As[lk + 1][lr + rr * 32] = a4.y;
            As[lk + 2][lr + rr * 32] = a4.z;
            As[lk + 3][lr + rr * 32] = a4.w;

            int n = n0 + lr + rr * 32;
            float4 b4 = *(const float4*)(W + (size_t)n * 256 + k0 + lk);
            Bs[lk + 0][lr + rr * 32] = b4.x;
            Bs[lk + 1][lr + rr * 32] = b4.y;
            Bs[lk + 2][lr + rr * 32] = b4.z;
            Bs[lk + 3][lr + rr * 32] = b4.w;
        }
        __syncthreads();

        #pragma unroll
        for (int kk = 0; kk < 32; kk++) {
            float a[4], b[4];
            *(float4*)a = *(const float4*)&As[kk][ty << 2];
            *(float4*)b = *(const float4*)&Bs[kk][tx << 2];
            #pragma unroll
            for (int i = 0; i < 4; i++)
                #pragma unroll
                for (int j = 0; j < 4; j++)
                    acc[i][j] = fmaf(a[i], b[j], acc[i][j]);
        }
        __syncthreads();
    }

    float4 bv = *(const float4*)(bias + n0 + (tx << 2));
    #pragma unroll
    for (int i = 0; i < 4; i++) {
        int m = m0 + (ty << 2) + i;
        float4 o;
        o.x = acc[i][0] + bv.x;
        o.y = acc[i][1] + bv.y;
        o.z = acc[i][2] + bv.z;
        o.w = acc[i][3] + bv.w;
        *(float4*)(g_xp + (size_t)m * 256 + n0 + (tx << 2)) = o;
    }
}

// ---------------------------------------------------------------------------
// LTC scan: 4-CTA clusters, 32 clusters (128 CTAs), 2 batch elems / cluster.
//   - Masked recurrent weights in registers (32 f32x2 / thread), f32x2 GEMV.
//   - Cross-CTA h exchange: producers STS their 512-B rank block locally,
//     bar.sync, fence.proxy.async, then ONE thread issues 3 bulk DSMEM copies
//     (cp.async.bulk.shared::cluster.shared::cta) with mbarrier complete_tx.
//     => 3 tx events per barrier per step instead of 512 scalar st.async.
//   - Two alternating mbarriers (even/odd step) kill the 1-step-skew race.
//   - tanh.approx.f32; xq prefetched one step ahead; out STG spread to
//     ks=1/ks=2 lanes (off critical path).
// ---------------------------------------------------------------------------
#define CS   4
#define BLK  132     // floats per rank block: 128 data (64 b0 | 64 b1) + 4 pad
#define BLKB (BLK*4) // 528 bytes (16-aligned, 528%128=16 -> conflict-free)

typedef unsigned long long u64t;

__device__ __forceinline__ uint32_t smem_u32(const void* p) {
    return (uint32_t)__cvta_generic_to_shared(p);
}
__device__ __forceinline__ u64t pk2(float x, float y) {
    u64t r; asm("mov.b64 %0, {%1,%2};" : "=l"(r) : "f"(x), "f"(y)); return r;
}
__device__ __forceinline__ void fma2(u64t& d, u64t a, u64t b) {
    asm("fma.rn.f32x2 %0, %1, %2, %0;" : "+l"(d) : "l"(a), "l"(b));
}
__device__ __forceinline__ float hsum2(u64t v) {
    float a, b; asm("mov.b64 {%0,%1}, %2;" : "=f"(a), "=f"(b) : "l"(v));
    return a + b;
}
__device__ __forceinline__ float tanh_fast(float x) {
    float y; asm("tanh.approx.f32 %0, %1;" : "=f"(y) : "f"(x)); return y;
}
__device__ __forceinline__ void mbar_wait(uint32_t mb, uint32_t par) {
    asm volatile(
        "{ .reg .pred p;\n\t"
        "WAIT_%=:\n\t"
        "  mbarrier.try_wait.parity.acquire.cluster.shared::cta.b64 p, [%0], %1, 0x989680;\n\t"
        "  @!p bra WAIT_%=;\n\t"
        "}" :: "r"(mb), "r"(par) : "memory");
}

__global__ void __cluster_dims__(CS, 1, 1) __launch_bounds__(256, 1)
ltc_scan(const float* __restrict__ Wrec, const float* __restrict__ mask,
         const float* __restrict__ tau_raw, float* __restrict__ out,
         int outoff)
{
    // 3 time-buffers x 4 rank-blocks x BLK floats
    __shared__ __align__(16) float hb[3][CS][BLK];
    __shared__ u64t mbar[2];

    uint32_t rank;
    asm("mov.u32 %0, %%cluster_ctarank;" : "=r"(rank));
    const int cl = blockIdx.x / CS;
    const int b0 = cl * 2;
    const int b1 = b0 + 1;

    const int tid  = threadIdx.x;
    const int lane = tid & 31;
    const int warp = tid >> 5;
    const int jl   = lane & 7;      // neuron within warp
    const int ks   = lane >> 3;     // k-slice (= source rank block) 0..3
    const int j    = warp * 8 + jl; // local neuron 0..63
    const int jf   = (int)rank * 64 + j;   // global neuron 0..255

    const uint32_t mb_u32[2] = { smem_u32(&mbar[0]), smem_u32(&mbar[1]) };
    if (tid == 0) {
        asm volatile("mbarrier.init.shared.b64 [%0], 1;" :: "r"(mb_u32[0]) : "memory");
        asm volatile("mbarrier.init.shared.b64 [%0], 1;" :: "r"(mb_u32[1]) : "memory");
    }

    // Zero all h buffers.
    for (int e = tid; e < 3 * CS * BLK; e += 256)
        ((float*)hb)[e] = 0.f;

    // DSMEM rank-address deltas (mapa is affine in the address).
    int32_t dsd[CS];
    #pragma unroll
    for (int c = 0; c < CS; c++) {
        uint32_t ra;
        asm("mapa.shared::cluster.u32 %0, %1, %2;" : "=r"(ra) : "r"(mb_u32[0]), "r"(c));
        dsd[c] = (int32_t)(ra - mb_u32[0]);
    }

    // This thread's 64 masked weights (k in [ks*64, ks*64+64)) as 32 f32x2.
    u64t w2[32];
    {
        const float4* wr = (const float4*)(Wrec + (size_t)jf * HH + ks * 64);
        const float4* mr = (const float4*)(mask + (size_t)jf * HH + ks * 64);
        #pragma unroll
        for (int ii = 0; ii < 16; ii++) {
            float4 wv = __ldg(wr + ii);
            float4 mv = __ldg(mr + ii);
            w2[2 * ii + 0] = pk2(wv.x * mv.x, wv.y * mv.y);
            w2[2 * ii + 1] = pk2(wv.z * mv.z, wv.w * mv.w);
        }
    }

    const float tr     = tau_raw[jf];
    const float invtau = 1.0f / (log1pf(expf(tr)) + 0.1f);

    const float* xp0 = g_xp + (size_t)(b0 * TT) * HH + jf;
    const float* xp1 = g_xp + (size_t)(b1 * TT) * HH + jf;
    float* out0 = out + (size_t)(b0 * TT) * 512 + outoff + jf;
    float* out1 = out + (size_t)(b1 * TT) * 512 + outoff + jf;

    __syncthreads();
    asm volatile("barrier.cluster.arrive.aligned;" ::: "memory");
    asm volatile("barrier.cluster.wait.aligned;"   ::: "memory");

    // Prefetch xq for t=0 (all lanes; same address across ks -> broadcast).
    float xq0 = __ldg(xp0);
    float xq1 = __ldg(xp1);

    int wb = 0, rb = 2;

    for (int t = 0; t < TT; t++) {
        const uint32_t mbx = mb_u32[t & 1];
        if (tid == 0)
            asm volatile("mbarrier.arrive.expect_tx.shared.b64 _, [%0], 1536;"
                         :: "r"(mbx) : "memory");

        // h_old for this thread's neuron (independent of GEMV accumulators).
        const float* rblk = &hb[rb][rank][0];
        float h0o = rblk[j];
        float h1o = rblk[64 + j];

        // GEMV slice over source block ks (k = ks*64 .. ks*64+63).
        const ulonglong2* p0 = (const ulonglong2*)(&hb[rb][ks][0]);
        const ulonglong2* p1 = (const ulonglong2*)(&hb[rb][ks][64]);
        u64t a0 = 0, a1 = 0, c0 = 0, c1 = 0;
        #pragma unroll
        for (int ii = 0; ii < 16; ii++) {
            ulonglong2 v0 = p0[ii];
            ulonglong2 v1 = p1[ii];
            fma2(a0, w2[2 * ii + 0], v0.x);
            fma2(a1, w2[2 * ii + 1], v0.y);
            fma2(c0, w2[2 * ii + 0], v1.x);
            fma2(c1, w2[2 * ii + 1], v1.y);
        }
        float s0 = hsum2(a0) + hsum2(a1);
        float s1 = hsum2(c0) + hsum2(c1);
        s0 += __shfl_xor_sync(0xffffffffu, s0, 8);
        s0 += __shfl_xor_sync(0xffffffffu, s0, 16);
        s1 += __shfl_xor_sync(0xffffffffu, s1, 8);
        s1 += __shfl_xor_sync(0xffffffffu, s1, 16);

        // Every lane now has the full sums; compute the update redundantly.
        float hn0 = fmaf(tanh_fast(s0 + xq0) - h0o, invtau, h0o);
        float hn1 = fmaf(tanh_fast(s1 + xq1) - h1o, invtau, h1o);

        // ks==0 lanes publish locally; critical path continues to bar.sync.
        float* wblk = &hb[wb][rank][0];
        if (ks == 0) {
            wblk[j]      = hn0;
            wblk[64 + j] = hn1;
        }
        __syncthreads();

        if (tid == 0) {
            asm volatile("fence.proxy.async.shared::cta;" ::: "memory");
            const uint32_t src = smem_u32(wblk);
            #pragma unroll
            for (int c = 1; c < CS; c++) {
                const int peer = ((int)rank + c) & 3;
                asm volatile(
                    "cp.async.bulk.shared::cluster.shared::cta.mbarrier::complete_tx::bytes "
                    "[%0], [%1], 512, [%2];"
                    :: "r"(src + dsd[peer]), "r"(src), "r"(mbx + dsd[peer])
                    : "memory");
            }
        }

        // Off-critical-path work while the bulk copies fly.
        if (ks == 1) out0[(size_t)t * 512] = hn0;
        if (ks == 2) out1[(size_t)t * 512] = hn1;
        if (t + 1 < TT) {
            xq0 = __ldg(xp0 + (size_t)(t + 1) * HH);
            xq1 = __ldg(xp1 + (size_t)(t + 1) * HH);
        }

        mbar_wait(mbx, (uint32_t)((t >> 1) & 1));

        rb = wb;
        wb = (wb == 2) ? 0 : wb + 1;
    }

    // Don't exit while peers' bulk reads of our SMEM may be in flight.
    asm volatile("barrier.cluster.arrive.aligned;" ::: "memory");
    asm volatile("barrier.cluster.wait.aligned;"   ::: "memory");
}

// ---------------------------------------------------------------------------
// Launch: gemm(xp0) -> scan0 -> gemm(xp1 from h0 in d_out) -> scan1
// ---------------------------------------------------------------------------
extern "C" void kernel_launch(void* const* d_in, const int* in_sizes, int n_in,
                              void* d_out, int out_size)
{
    const int*   tokens = (const int*)  d_in[0];
    const float* emb    = (const float*)d_in[1];
    const float* W_in0  = (const float*)d_in[2];
    const float* W_rec0 = (const float*)d_in[3];
    const float* b0     = (const float*)d_in[4];
    const float* tau0   = (const float*)d_in[5];
    const float* mask0  = (const float*)d_in[6];
    const float* W_in1  = (const float*)d_in[7];
    const float* W_rec1 = (const float*)d_in[8];
    const float* b1     = (const float*)d_in[9];
    const float* tau1   = (const float*)d_in[10];
    const float* mask1  = (const float*)d_in[11];
    float* out = (float*)d_out;

    (void)in_sizes; (void)n_in; (void)out_size;

    dim3 ggrid(BT / 64, HH / 64);   // 128 x 4

    gemm_xp<<<ggrid, 256>>>(emb, tokens, EE, W_in0, b0);
    ltc_scan<<<128, 256>>>(W_rec0, mask0, tau0, out, 0);
    gemm_xp<<<ggrid, 256>>>(out, nullptr, 512, W_in1, b1);
    ltc_scan<<<128, 256>>>(W_rec1, mask1, tau1, out, 256);
}